// round 14
// baseline (speedup 1.0000x reference)
#include <cuda_runtime.h>
#include <cuda_fp16.h>
#include <cstdint>

// W8A16 linear, single-pass fp16 mma.sync (compute_103-safe).
// out[M,N] = (x[M,K] @ W[N,K]^T) * scales[N] + bias[N]
//   Prequant (fused): W int8-in-int32 -> fp16 (exact); x fp32 -> fp16.
//   GEMM: 1 CTA x 256 thr, tile 128x256, warp tile 64x64, BK=64, 4-stage
//   cp.async + mbarrier pipeline (R11-exact schedule).
//   Wave-tail fix: tiles 0..1331 = 9 exact waves; last 44 tiles are
//   split-K x3 (132 CTAs, ~1/3 wave) -> partials in static scratch,
//   deterministic reduce kernel adds 3 partials + bias.

#define GK 4096
#define GM 4096
#define GN 11008

#define NXT 43                      // N tiles
#define NYT 32                      // M tiles
#define NTILES (NXT * NYT)          // 1376
#define NFULL 1332                  // 9 exact waves x 148
#define NTAIL (NTILES - NFULL)      // 44
#define SPLITK 3
#define GEMM_GRID (NFULL + NTAIL * SPLITK)   // 1464

__device__ __half g_xh[(size_t)GM * GK];
__device__ __half g_wh[(size_t)GN * GK];
__device__ float  g_part[(size_t)SPLITK * NTAIL * 128 * 256];   // 17.3 MB

// ---------------- helpers ----------------
__device__ __forceinline__ uint32_t s2u(const void* p) {
    uint32_t a;
    asm("{ .reg .u64 t; cvta.to.shared.u64 t, %1; cvt.u32.u64 %0, t; }" : "=r"(a) : "l"(p));
    return a;
}
#define CP_ASYNC16(dst, src) \
    asm volatile("cp.async.cg.shared.global [%0], [%1], 16;" :: "r"(dst), "l"(src))

#define LDSM_X4(r0, r1, r2, r3, a)                                              \
    asm volatile("ldmatrix.sync.aligned.m8n8.x4.shared.b16 {%0,%1,%2,%3}, [%4];" \
                 : "=r"(r0), "=r"(r1), "=r"(r2), "=r"(r3) : "r"(a))

#define MBARRIER_INIT(mb, c) \
    asm volatile("mbarrier.init.shared.b64 [%0], %1;" :: "r"((uint32_t)(mb)), "r"((uint32_t)(c)) : "memory")
#define MBARRIER_ARRIVE(mb) \
    asm volatile("mbarrier.arrive.shared.b64 _, [%0];" :: "r"((uint32_t)(mb)) : "memory")
#define CPASYNC_MBAR_ARRIVE(mb) \
    asm volatile("cp.async.mbarrier.arrive.noinc.shared::cta.b64 [%0];" :: "r"((uint32_t)(mb)) : "memory")

#define MBARRIER_WAIT_PARITY(mb, par) do {                                          \
    uint32_t _mb = (uint32_t)(mb); uint32_t _p = (uint32_t)(par); uint32_t _done;   \
    asm volatile("{\n\t.reg .pred p;\n\t"                                           \
        "mbarrier.try_wait.parity.acquire.cta.shared::cta.b64 p, [%1], %2;\n\t"     \
        "selp.b32 %0, 1, 0, p;\n\t}"                                                \
        : "=r"(_done) : "r"(_mb), "r"(_p) : "memory");                              \
    if (!_done) {                                                                   \
        asm volatile("{\n\t.reg .pred P1;\n\t"                                      \
            "WL_%=:\n\t"                                                            \
            "mbarrier.try_wait.parity.acquire.cta.shared::cta.b64 P1, [%0], %1, 0x989680;\n\t" \
            "@P1 bra.uni WD_%=;\n\t"                                                \
            "bra.uni WL_%=;\n\t"                                                    \
            "WD_%=:\n\t}"                                                           \
            :: "r"(_mb), "r"(_p) : "memory");                                       \
    }                                                                               \
} while (0)

// tile index -> (xg, yg) swizzle (SWZ_G = 8; 1376 = 4 stripes x 344)
__device__ __forceinline__ void tile_to_xy(int tile, int& xg, int& yg) {
    const int tps = 8 * NXT;            // 344
    int stripe = tile / tps;
    int rem    = tile - stripe * tps;
    xg = rem >> 3;
    yg = stripe * 8 + (rem & 7);
}

// ---------------- fused prequant ----------------
#define WPQ_BLOCKS 2048
#define XPQ_BLOCKS 1024
__global__ void prequant_kernel(const int* __restrict__ w,
                                const float* __restrict__ x,
                                int n4w, int n4x) {
    const int bid = blockIdx.x;
    if (bid < WPQ_BLOCKS) {
        int stride = WPQ_BLOCKS * blockDim.x;
        for (int i = bid * blockDim.x + threadIdx.x; i < n4w; i += stride) {
            int4 v = reinterpret_cast<const int4*>(w)[i];
            __half2 p0 = __floats2half2_rn((float)v.x, (float)v.y);   // exact
            __half2 p1 = __floats2half2_rn((float)v.z, (float)v.w);
            uint2 pk;
            pk.x = *reinterpret_cast<uint32_t*>(&p0);
            pk.y = *reinterpret_cast<uint32_t*>(&p1);
            reinterpret_cast<uint2*>(g_wh)[i] = pk;
        }
    } else {
        int stride = XPQ_BLOCKS * blockDim.x;
        for (int i = (bid - WPQ_BLOCKS) * blockDim.x + threadIdx.x; i < n4x; i += stride) {
            float4 v = reinterpret_cast<const float4*>(x)[i];
            __half2 p0 = __floats2half2_rn(v.x, v.y);
            __half2 p1 = __floats2half2_rn(v.z, v.w);
            uint2 pk;
            pk.x = *reinterpret_cast<uint32_t*>(&p0);
            pk.y = *reinterpret_cast<uint32_t*>(&p1);
            reinterpret_cast<uint2*>(g_xh)[i] = pk;
        }
    }
}

// ---------------- GEMM ----------------
#define BM 128
#define BN 256
#define BK 64
#define NTHR 256
#define ATILE 16384                 // 128 rows x 128 B
#define BTILE 32768                 // 256 rows x 128 B
#define STAGEB (ATILE + BTILE)      // 49152
#define NSTAGE 4
#define STAGES_B (NSTAGE * STAGEB)  // 196608
#define SMEMB (STAGES_B + 128)      // + mbarriers

__global__ __launch_bounds__(NTHR, 1)
void w8a16_hmma_kernel(const float* __restrict__ scales,
                       const float* __restrict__ bias,
                       float* __restrict__ out,
                       int M, int N, int K)
{
    extern __shared__ char sm[];
    const uint32_t sb = s2u(sm);
    const uint32_t mb_full  = sb + STAGES_B;        // 4 x 8B
    const uint32_t mb_empty = sb + STAGES_B + 32;   // 4 x 8B
    const int tid  = threadIdx.x;
    const int lane = tid & 31;
    const int warp = tid >> 5;
    const int wm = warp >> 2;            // 0..1 -> m offset 64*wm
    const int wn = warp & 3;             // 0..3 -> n offset 64*wn

    // ---- work assignment: normal tile or split-K tail part ----
    const int lb = blockIdx.x;
    int tile, part, kbeg, nch;
    if (lb < NFULL) {
        tile = lb; part = -1; kbeg = 0; nch = K / BK;            // 64
    } else {
        int idx = lb - NFULL;
        tile = NFULL + idx / SPLITK;
        part = idx % SPLITK;
        // 64 chunks split 22/21/21
        kbeg = (part == 0) ? 0 : (part == 1 ? 22 : 43);
        nch  = (part == 0) ? 22 : 21;
    }
    int xg, yg;
    tile_to_xy(tile, xg, yg);
    const int mbase = yg * BM;
    const int nbase = xg * BN;

    const __half* ag  = g_xh + (size_t)mbase * K;
    const __half* bgp = g_wh + (size_t)nbase * K;

    // ---- mbarrier init ----
    if (tid == 0) {
        #pragma unroll
        for (int s = 0; s < NSTAGE; ++s) {
            MBARRIER_INIT(mb_full  + s * 8, NTHR);
            MBARRIER_INIT(mb_empty + s * 8, 8);
        }
    }
    __syncthreads();

    float acc[4][8][4];
    #pragma unroll
    for (int mi = 0; mi < 4; ++mi)
        #pragma unroll
        for (int ni = 0; ni < 8; ++ni)
            #pragma unroll
            for (int c = 0; c < 4; ++c)
                acc[mi][ni][c] = 0.0f;

    // ldmatrix lane address components (non-trans x4 for both operands)
    const int a_rl = (lane & 7) + ((lane >> 3) & 1) * 8;
    const int a_cb = lane >> 4;
    const int b_rl = (lane & 7) + ((lane >> 4) << 3);
    const int b_cb = (lane >> 3) & 1;

    uint32_t arow[4], am7[4];
    #pragma unroll
    for (int mi = 0; mi < 4; ++mi) {
        int r = wm * 64 + mi * 16 + a_rl;
        arow[mi] = (uint32_t)r * 128;
        am7[mi]  = (uint32_t)(r & 7);
    }
    uint32_t brow[4], bm7[4];
    #pragma unroll
    for (int nj = 0; nj < 4; ++nj) {
        int r = wn * 64 + nj * 16 + b_rl;
        brow[nj] = (uint32_t)r * 128;
        bm7[nj]  = (uint32_t)(r & 7);
    }

    #define ISSUE_STAGE(st, k0) do {                                             \
        uint32_t dstb = sb + (st) * STAGEB;                                      \
        _Pragma("unroll")                                                        \
        for (int cc = 0; cc < 12; ++cc) {                                        \
            int cid  = tid + cc * NTHR;         /* 0..3071 */                    \
            int isB  = cid >= 1024;                                              \
            int rem2 = isB ? (cid - 1024) : cid;                                 \
            int row  = rem2 >> 3;                                                \
            int c    = rem2 & 7;                                                 \
            const __half* src = (isB ? bgp : ag) + (size_t)row * K + (k0) + c * 8; \
            uint32_t dst = dstb + (isB ? ATILE : 0) + row * 128 +                \
                           ((uint32_t)(c ^ (row & 7)) << 4);                     \
            CP_ASYNC16(dst, src);                                                \
        }                                                                        \
        CPASYNC_MBAR_ARRIVE(mb_full + (st) * 8);                                 \
    } while (0)

    // prologue: fill 4 stages with chunks kbeg..kbeg+3
    ISSUE_STAGE(0, kbeg * BK);
    ISSUE_STAGE(1, (kbeg + 1) * BK);
    ISSUE_STAGE(2, (kbeg + 2) * BK);
    ISSUE_STAGE(3, (kbeg + 3) * BK);

    for (int i = 0; i < nch; ++i) {
        const int s = i & 3;
        const int q = i >> 2;

        MBARRIER_WAIT_PARITY(mb_full + s * 8, q & 1);

        const uint32_t as = sb + s * STAGEB;
        const uint32_t bs = as + ATILE;

        #pragma unroll
        for (int ks = 0; ks < 4; ++ks) {
            const uint32_t kc2 = (uint32_t)(ks * 2);

            uint32_t bf[4][4];
            #pragma unroll
            for (int nj = 0; nj < 4; ++nj) {
                uint32_t addr = bs + brow[nj] + (((kc2 + b_cb) ^ bm7[nj]) << 4);
                LDSM_X4(bf[nj][0], bf[nj][1], bf[nj][2], bf[nj][3], addr);
            }
            uint32_t af[4][4];
            #pragma unroll
            for (int mi = 0; mi < 4; ++mi) {
                uint32_t addr = as + arow[mi] + (((kc2 + a_cb) ^ am7[mi]) << 4);
                LDSM_X4(af[mi][0], af[mi][1], af[mi][2], af[mi][3], addr);
            }

            #pragma unroll
            for (int mi = 0; mi < 4; ++mi) {
                #pragma unroll
                for (int nj = 0; nj < 4; ++nj) {
                    #pragma unroll
                    for (int h = 0; h < 2; ++h) {
                        const int ni = nj * 2 + h;
                        asm volatile(
                            "mma.sync.aligned.m16n8k16.row.col.f32.f16.f16.f32 "
                            "{%0,%1,%2,%3}, {%4,%5,%6,%7}, {%8,%9}, {%0,%1,%2,%3};\n"
                            : "+f"(acc[mi][ni][0]), "+f"(acc[mi][ni][1]),
                              "+f"(acc[mi][ni][2]), "+f"(acc[mi][ni][3])
                            : "r"(af[mi][0]), "r"(af[mi][1]),
                              "r"(af[mi][2]), "r"(af[mi][3]),
                              "r"(bf[nj][h * 2]), "r"(bf[nj][h * 2 + 1]));
                    }
                }
            }
        }

        if (lane == 0) MBARRIER_ARRIVE(mb_empty + s * 8);

        const int j = i + 4;
        if (j < nch) {
            MBARRIER_WAIT_PARITY(mb_empty + s * 8, q & 1);
            ISSUE_STAGE(s, (kbeg + j) * BK);
        }
    }

    // ---- epilogue ----
    if (part < 0) {
        // normal tile: y = acc * scales[n] + bias[n]
        #pragma unroll
        for (int mi = 0; mi < 4; ++mi) {
            const int r0 = mbase + wm * 64 + mi * 16 + (lane >> 2);
            float* o0 = out + (size_t)r0 * N + nbase;
            float* o1 = out + (size_t)(r0 + 8) * N + nbase;
            #pragma unroll
            for (int ni = 0; ni < 8; ++ni) {
                const int gn = wn * 64 + ni * 8 + ((lane & 3) << 1);
                const float s0 = scales[nbase + gn], s1 = scales[nbase + gn + 1];
                const float b0 = bias[nbase + gn],   b1 = bias[nbase + gn + 1];
                float2 v;
                v.x = acc[mi][ni][0] * s0 + b0;
                v.y = acc[mi][ni][1] * s1 + b1;
                *reinterpret_cast<float2*>(o0 + gn) = v;
                v.x = acc[mi][ni][2] * s0 + b0;
                v.y = acc[mi][ni][3] * s1 + b1;
                *reinterpret_cast<float2*>(o1 + gn) = v;
            }
        }
    } else {
        // split-K partial: scale applied, bias added later by reduce kernel
        const int z = tile - NFULL;
        float* pb = g_part + ((size_t)part * NTAIL + z) * 128 * 256;
        #pragma unroll
        for (int mi = 0; mi < 4; ++mi) {
            const int r0 = wm * 64 + mi * 16 + (lane >> 2);
            float* o0 = pb + (size_t)r0 * 256;
            float* o1 = pb + (size_t)(r0 + 8) * 256;
            #pragma unroll
            for (int ni = 0; ni < 8; ++ni) {
                const int gn = wn * 64 + ni * 8 + ((lane & 3) << 1);
                const float s0 = scales[nbase + gn], s1 = scales[nbase + gn + 1];
                float2 v;
                v.x = acc[mi][ni][0] * s0;
                v.y = acc[mi][ni][1] * s1;
                *reinterpret_cast<float2*>(o0 + gn) = v;
                v.x = acc[mi][ni][2] * s0;
                v.y = acc[mi][ni][3] * s1;
                *reinterpret_cast<float2*>(o1 + gn) = v;
            }
        }
    }
}

// ---------------- tail reduce: out = p0+p1+p2 + bias ----------------
__global__ __launch_bounds__(256)
void tailreduce_kernel(const float* __restrict__ bias,
                       float* __restrict__ out, int N) {
    const int z  = blockIdx.x >> 3;        // 0..43
    const int rg = blockIdx.x & 7;         // row group (16 rows)
    const int tid = threadIdx.x;
    int xg, yg;
    tile_to_xy(NFULL + z, xg, yg);
    const int mbase = yg * BM;
    const int nbase = xg * BN;
    const float b = bias[nbase + tid];
    const float* p0 = g_part + ((size_t)0 * NTAIL + z) * 128 * 256;
    const float* p1 = g_part + ((size_t)1 * NTAIL + z) * 128 * 256;
    const float* p2 = g_part + ((size_t)2 * NTAIL + z) * 128 * 256;
    #pragma unroll
    for (int r = 0; r < 16; ++r) {
        const int row = rg * 16 + r;
        const int off = row * 256 + tid;
        out[(size_t)(mbase + row) * N + nbase + tid] = p0[off] + p1[off] + p2[off] + b;
    }
}

extern "C" void kernel_launch(void* const* d_in, const int* in_sizes, int n_in,
                              void* d_out, int out_size)
{
    const float* x      = (const float*) d_in[0];
    const int*   w      = (const int*)   d_in[1];   // int8 values in int32 storage
    const float* scales = (const float*) d_in[2];
    const float* bias   = (const float*) d_in[3];
    float*       out    = (float*)       d_out;

    const int N = in_sizes[2];            // 11008
    const int K = in_sizes[1] / N;        // 4096
    const int M = in_sizes[0] / K;        // 4096

    cudaFuncSetAttribute(w8a16_hmma_kernel,
                         cudaFuncAttributeMaxDynamicSharedMemorySize, SMEMB);

    prequant_kernel<<<WPQ_BLOCKS + XPQ_BLOCKS, 256>>>(w, x, (N * K) / 4, (M * K) / 4);
    w8a16_hmma_kernel<<<GEMM_GRID, NTHR, SMEMB>>>(scales, bias, out, M, N, K);
    tailreduce_kernel<<<NTAIL * 8, 256>>>(bias, out, N);
}

// round 15
// speedup vs baseline: 1.4858x; 1.4858x over previous
#include <cuda_runtime.h>
#include <cuda_fp16.h>
#include <cstdint>

// W8A16 linear, single-pass fp16 mma.sync (compute_103-safe).
// out[M,N] = (x[M,K] @ W[N,K]^T) * scales[N] + bias[N]
//   Prequant: W int8-in-int32 -> fp16 (exact); x fp32 -> fp16 (rel err 2^-11).
//   GEMM: 1 CTA x 256 thr, tile 128x256, warp tile 64x64, BK=64, 4-stage
//   cp.async + mbarrier pipeline (R11-exact schedule).
//   Wave-tail: tiles 0..1331 = 9 exact waves of 148; last 44 tiles are
//   split-K x3 -> partials in static scratch, deterministic reduce adds bias.
//   R15: UNIFIED epilogue (obase/ostride/bmul) to avoid the R14 register
//   spill from duplicated store paths.

#define GK 4096
#define GM 4096
#define GN 11008

#define NXT 43                      // N tiles
#define NYT 32                      // M tiles
#define NTILES (NXT * NYT)          // 1376
#define NFULL 1332                  // 9 exact waves x 148
#define NTAIL (NTILES - NFULL)      // 44
#define SPLITK 3
#define GEMM_GRID (NFULL + NTAIL * SPLITK)   // 1464

__device__ __half g_xh[(size_t)GM * GK];
__device__ __half g_wh[(size_t)GN * GK];
__device__ float  g_part[(size_t)SPLITK * NTAIL * 128 * 256];   // 17.3 MB

// ---------------- helpers ----------------
__device__ __forceinline__ uint32_t s2u(const void* p) {
    uint32_t a;
    asm("{ .reg .u64 t; cvta.to.shared.u64 t, %1; cvt.u32.u64 %0, t; }" : "=r"(a) : "l"(p));
    return a;
}
#define CP_ASYNC16(dst, src) \
    asm volatile("cp.async.cg.shared.global [%0], [%1], 16;" :: "r"(dst), "l"(src))

#define LDSM_X4(r0, r1, r2, r3, a)                                              \
    asm volatile("ldmatrix.sync.aligned.m8n8.x4.shared.b16 {%0,%1,%2,%3}, [%4];" \
                 : "=r"(r0), "=r"(r1), "=r"(r2), "=r"(r3) : "r"(a))

#define MBARRIER_INIT(mb, c) \
    asm volatile("mbarrier.init.shared.b64 [%0], %1;" :: "r"((uint32_t)(mb)), "r"((uint32_t)(c)) : "memory")
#define MBARRIER_ARRIVE(mb) \
    asm volatile("mbarrier.arrive.shared.b64 _, [%0];" :: "r"((uint32_t)(mb)) : "memory")
#define CPASYNC_MBAR_ARRIVE(mb) \
    asm volatile("cp.async.mbarrier.arrive.noinc.shared::cta.b64 [%0];" :: "r"((uint32_t)(mb)) : "memory")

#define MBARRIER_WAIT_PARITY(mb, par) do {                                          \
    uint32_t _mb = (uint32_t)(mb); uint32_t _p = (uint32_t)(par); uint32_t _done;   \
    asm volatile("{\n\t.reg .pred p;\n\t"                                           \
        "mbarrier.try_wait.parity.acquire.cta.shared::cta.b64 p, [%1], %2;\n\t"     \
        "selp.b32 %0, 1, 0, p;\n\t}"                                                \
        : "=r"(_done) : "r"(_mb), "r"(_p) : "memory");                              \
    if (!_done) {                                                                   \
        asm volatile("{\n\t.reg .pred P1;\n\t"                                      \
            "WL_%=:\n\t"                                                            \
            "mbarrier.try_wait.parity.acquire.cta.shared::cta.b64 P1, [%0], %1, 0x989680;\n\t" \
            "@P1 bra.uni WD_%=;\n\t"                                                \
            "bra.uni WL_%=;\n\t"                                                    \
            "WD_%=:\n\t}"                                                           \
            :: "r"(_mb), "r"(_p) : "memory");                                       \
    }                                                                               \
} while (0)

// tile index -> (xg, yg) swizzle (SWZ_G = 8)
__device__ __forceinline__ void tile_to_xy(int tile, int& xg, int& yg) {
    const int tps = 8 * NXT;            // 344
    int stripe = tile / tps;
    int rem    = tile - stripe * tps;
    xg = rem >> 3;
    yg = stripe * 8 + (rem & 7);
}

// ---------------- prequant (two kernels, as R11) ----------------
__global__ void wprequant_kernel(const int* __restrict__ w, int n4) {
    int stride = gridDim.x * blockDim.x;
    for (int i = blockIdx.x * blockDim.x + threadIdx.x; i < n4; i += stride) {
        int4 v = reinterpret_cast<const int4*>(w)[i];
        __half2 p0 = __floats2half2_rn((float)v.x, (float)v.y);   // exact
        __half2 p1 = __floats2half2_rn((float)v.z, (float)v.w);
        uint2 pk;
        pk.x = *reinterpret_cast<uint32_t*>(&p0);
        pk.y = *reinterpret_cast<uint32_t*>(&p1);
        reinterpret_cast<uint2*>(g_wh)[i] = pk;
    }
}

__global__ void xprequant_kernel(const float* __restrict__ x, int n4) {
    int stride = gridDim.x * blockDim.x;
    for (int i = blockIdx.x * blockDim.x + threadIdx.x; i < n4; i += stride) {
        float4 v = reinterpret_cast<const float4*>(x)[i];
        __half2 p0 = __floats2half2_rn(v.x, v.y);
        __half2 p1 = __floats2half2_rn(v.z, v.w);
        uint2 pk;
        pk.x = *reinterpret_cast<uint32_t*>(&p0);
        pk.y = *reinterpret_cast<uint32_t*>(&p1);
        reinterpret_cast<uint2*>(g_xh)[i] = pk;
    }
}

// ---------------- GEMM ----------------
#define BM 128
#define BN 256
#define BK 64
#define NTHR 256
#define ATILE 16384                 // 128 rows x 128 B
#define BTILE 32768                 // 256 rows x 128 B
#define STAGEB (ATILE + BTILE)      // 49152
#define NSTAGE 4
#define STAGES_B (NSTAGE * STAGEB)  // 196608
#define SMEMB (STAGES_B + 128)      // + mbarriers

__global__ __launch_bounds__(NTHR, 1)
void w8a16_hmma_kernel(const float* __restrict__ scales,
                       const float* __restrict__ bias,
                       float* __restrict__ out,
                       int M, int N, int K)
{
    extern __shared__ char sm[];
    const uint32_t sb = s2u(sm);
    const uint32_t mb_full  = sb + STAGES_B;        // 4 x 8B
    const uint32_t mb_empty = sb + STAGES_B + 32;   // 4 x 8B
    const int tid  = threadIdx.x;
    const int lane = tid & 31;
    const int warp = tid >> 5;
    const int wm = warp >> 2;            // 0..1 -> m offset 64*wm
    const int wn = warp & 3;             // 0..3 -> n offset 64*wn

    // ---- work assignment ----
    const int lb = blockIdx.x;
    int tile, part, kbeg, nch;
    if (lb < NFULL) {
        tile = lb; part = -1; kbeg = 0; nch = K / BK;            // 64
    } else {
        int idx = lb - NFULL;
        tile = NFULL + idx / SPLITK;
        part = idx % SPLITK;
        kbeg = (part == 0) ? 0 : (part == 1 ? 22 : 43);          // 22/21/21
        nch  = (part == 0) ? 22 : 21;
    }
    int xg, yg;
    tile_to_xy(tile, xg, yg);
    const int mbase = yg * BM;
    const int nbase = xg * BN;

    // unified epilogue parameters
    float*  obase;
    int     ostride;
    float   bmul;
    if (part < 0) {
        obase   = out + (size_t)mbase * N + nbase;
        ostride = N;
        bmul    = 1.0f;
    } else {
        obase   = g_part + ((size_t)part * NTAIL + (tile - NFULL)) * 128 * 256;
        ostride = 256;
        bmul    = 0.0f;
    }

    const __half* ag  = g_xh + (size_t)mbase * K;
    const __half* bgp = g_wh + (size_t)nbase * K;

    // ---- mbarrier init ----
    if (tid == 0) {
        #pragma unroll
        for (int s = 0; s < NSTAGE; ++s) {
            MBARRIER_INIT(mb_full  + s * 8, NTHR);
            MBARRIER_INIT(mb_empty + s * 8, 8);
        }
    }
    __syncthreads();

    float acc[4][8][4];
    #pragma unroll
    for (int mi = 0; mi < 4; ++mi)
        #pragma unroll
        for (int ni = 0; ni < 8; ++ni)
            #pragma unroll
            for (int c = 0; c < 4; ++c)
                acc[mi][ni][c] = 0.0f;

    // ldmatrix lane address components (non-trans x4 for both operands)
    const int a_rl = (lane & 7) + ((lane >> 3) & 1) * 8;
    const int a_cb = lane >> 4;
    const int b_rl = (lane & 7) + ((lane >> 4) << 3);
    const int b_cb = (lane >> 3) & 1;

    uint32_t arow[4], am7[4];
    #pragma unroll
    for (int mi = 0; mi < 4; ++mi) {
        int r = wm * 64 + mi * 16 + a_rl;
        arow[mi] = (uint32_t)r * 128;
        am7[mi]  = (uint32_t)(r & 7);
    }
    uint32_t brow[4], bm7[4];
    #pragma unroll
    for (int nj = 0; nj < 4; ++nj) {
        int r = wn * 64 + nj * 16 + b_rl;
        brow[nj] = (uint32_t)r * 128;
        bm7[nj]  = (uint32_t)(r & 7);
    }

    #define ISSUE_STAGE(st, k0) do {                                             \
        uint32_t dstb = sb + (st) * STAGEB;                                      \
        _Pragma("unroll")                                                        \
        for (int cc = 0; cc < 12; ++cc) {                                        \
            int cid  = tid + cc * NTHR;         /* 0..3071 */                    \
            int isB  = cid >= 1024;                                              \
            int rem2 = isB ? (cid - 1024) : cid;                                 \
            int row  = rem2 >> 3;                                                \
            int c    = rem2 & 7;                                                 \
            const __half* src = (isB ? bgp : ag) + (size_t)row * K + (k0) + c * 8; \
            uint32_t dst = dstb + (isB ? ATILE : 0) + row * 128 +                \
                           ((uint32_t)(c ^ (row & 7)) << 4);                     \
            CP_ASYNC16(dst, src);                                                \
        }                                                                        \
        CPASYNC_MBAR_ARRIVE(mb_full + (st) * 8);                                 \
    } while (0)

    // prologue: fill 4 stages with chunks kbeg..kbeg+3
    ISSUE_STAGE(0, kbeg * BK);
    ISSUE_STAGE(1, (kbeg + 1) * BK);
    ISSUE_STAGE(2, (kbeg + 2) * BK);
    ISSUE_STAGE(3, (kbeg + 3) * BK);

    for (int i = 0; i < nch; ++i) {
        const int s = i & 3;
        const int q = (i >> 2) & 1;

        MBARRIER_WAIT_PARITY(mb_full + s * 8, q);

        const uint32_t as = sb + s * STAGEB;
        const uint32_t bs = as + ATILE;

        #pragma unroll
        for (int ks = 0; ks < 4; ++ks) {
            const uint32_t kc2 = (uint32_t)(ks * 2);

            uint32_t bf[4][4];
            #pragma unroll
            for (int nj = 0; nj < 4; ++nj) {
                uint32_t addr = bs + brow[nj] + (((kc2 + b_cb) ^ bm7[nj]) << 4);
                LDSM_X4(bf[nj][0], bf[nj][1], bf[nj][2], bf[nj][3], addr);
            }
            uint32_t af[4][4];
            #pragma unroll
            for (int mi = 0; mi < 4; ++mi) {
                uint32_t addr = as + arow[mi] + (((kc2 + a_cb) ^ am7[mi]) << 4);
                LDSM_X4(af[mi][0], af[mi][1], af[mi][2], af[mi][3], addr);
            }

            #pragma unroll
            for (int mi = 0; mi < 4; ++mi) {
                #pragma unroll
                for (int nj = 0; nj < 4; ++nj) {
                    #pragma unroll
                    for (int h = 0; h < 2; ++h) {
                        const int ni = nj * 2 + h;
                        asm volatile(
                            "mma.sync.aligned.m16n8k16.row.col.f32.f16.f16.f32 "
                            "{%0,%1,%2,%3}, {%4,%5,%6,%7}, {%8,%9}, {%0,%1,%2,%3};\n"
                            : "+f"(acc[mi][ni][0]), "+f"(acc[mi][ni][1]),
                              "+f"(acc[mi][ni][2]), "+f"(acc[mi][ni][3])
                            : "r"(af[mi][0]), "r"(af[mi][1]),
                              "r"(af[mi][2]), "r"(af[mi][3]),
                              "r"(bf[nj][h * 2]), "r"(bf[nj][h * 2 + 1]));
                    }
                }
            }
        }

        if (lane == 0) MBARRIER_ARRIVE(mb_empty + s * 8);

        const int j = i + 4;
        if (j < nch) {
            MBARRIER_WAIT_PARITY(mb_empty + s * 8, q);
            ISSUE_STAGE(s, (kbeg + j) * BK);
        }
    }

    // ---- unified epilogue: y = acc * scales[n] + bias[n]*bmul ----
    #pragma unroll
    for (int mi = 0; mi < 4; ++mi) {
        const int r0 = wm * 64 + mi * 16 + (lane >> 2);
        float* o0 = obase + (size_t)r0 * ostride;
        float* o1 = obase + (size_t)(r0 + 8) * ostride;
        #pragma unroll
        for (int ni = 0; ni < 8; ++ni) {
            const int gn = wn * 64 + ni * 8 + ((lane & 3) << 1);
            const float s0 = scales[nbase + gn], s1 = scales[nbase + gn + 1];
            const float b0 = bias[nbase + gn] * bmul;
            const float b1 = bias[nbase + gn + 1] * bmul;
            float2 v;
            v.x = acc[mi][ni][0] * s0 + b0;
            v.y = acc[mi][ni][1] * s1 + b1;
            *reinterpret_cast<float2*>(o0 + gn) = v;
            v.x = acc[mi][ni][2] * s0 + b0;
            v.y = acc[mi][ni][3] * s1 + b1;
            *reinterpret_cast<float2*>(o1 + gn) = v;
        }
    }
}

// ---------------- tail reduce: out = p0+p1+p2 + bias ----------------
__global__ __launch_bounds__(256)
void tailreduce_kernel(const float* __restrict__ bias,
                       float* __restrict__ out, int N) {
    const int z  = blockIdx.x >> 3;        // 0..43
    const int rg = blockIdx.x & 7;         // row group (16 rows)
    const int tid = threadIdx.x;
    int xg, yg;
    tile_to_xy(NFULL + z, xg, yg);
    const int mbase = yg * BM;
    const int nbase = xg * BN;
    const float b = bias[nbase + tid];
    const float* p0 = g_part + ((size_t)0 * NTAIL + z) * 128 * 256;
    const float* p1 = g_part + ((size_t)1 * NTAIL + z) * 128 * 256;
    const float* p2 = g_part + ((size_t)2 * NTAIL + z) * 128 * 256;
    #pragma unroll
    for (int r = 0; r < 16; ++r) {
        const int row = rg * 16 + r;
        const int off = row * 256 + tid;
        out[(size_t)(mbase + row) * N + nbase + tid] = p0[off] + p1[off] + p2[off] + b;
    }
}

extern "C" void kernel_launch(void* const* d_in, const int* in_sizes, int n_in,
                              void* d_out, int out_size)
{
    const float* x      = (const float*) d_in[0];
    const int*   w      = (const int*)   d_in[1];   // int8 values in int32 storage
    const float* scales = (const float*) d_in[2];
    const float* bias   = (const float*) d_in[3];
    float*       out    = (float*)       d_out;

    const int N = in_sizes[2];            // 11008
    const int K = in_sizes[1] / N;        // 4096
    const int M = in_sizes[0] / K;        // 4096

    cudaFuncSetAttribute(w8a16_hmma_kernel,
                         cudaFuncAttributeMaxDynamicSharedMemorySize, SMEMB);

    wprequant_kernel<<<2048, 256>>>(w, (N * K) / 4);
    xprequant_kernel<<<2048, 256>>>(x, (M * K) / 4);
    w8a16_hmma_kernel<<<GEMM_GRID, NTHR, SMEMB>>>(scales, bias, out, M, N, K);
    tailreduce_kernel<<<NTAIL * 8, 256>>>(bias, out, N);
}

// round 16
// speedup vs baseline: 1.4983x; 1.0084x over previous
#include <cuda_runtime.h>
#include <cuda_fp16.h>
#include <cstdint>

// W8A16 linear, single-pass fp16 mma.sync (compute_103-safe).
// out[M,N] = (x[M,K] @ W[N,K]^T) * scales[N] + bias[N]
//   Prequant: W int8-in-int32 -> fp16 (exact); x fp32 -> fp16 (rel err 2^-11).
//   GEMM: 1 CTA x 256 thr, tile 128x256, warp tile 64x64, BK=64, 4-stage
//   cp.async + mbarrier pipeline (R11-exact schedule).
//   Wave-tail: tiles 0..1331 = 9 exact waves of 148; last 44 tiles are
//   split-K x4 (16 chunks each) -> partials in static scratch; bias is
//   folded into the part-0 partial; reduce is a pure 4-way sum.

#define GK 4096
#define GM 4096
#define GN 11008

#define NXT 43                      // N tiles
#define NYT 32                      // M tiles
#define NTILES (NXT * NYT)          // 1376
#define NFULL 1332                  // 9 exact waves x 148
#define NTAIL (NTILES - NFULL)      // 44
#define SPLITK 4
#define GEMM_GRID (NFULL + NTAIL * SPLITK)   // 1508

__device__ __half g_xh[(size_t)GM * GK];
__device__ __half g_wh[(size_t)GN * GK];
__device__ float  g_part[(size_t)SPLITK * NTAIL * 128 * 256];   // 23 MB

// ---------------- helpers ----------------
__device__ __forceinline__ uint32_t s2u(const void* p) {
    uint32_t a;
    asm("{ .reg .u64 t; cvta.to.shared.u64 t, %1; cvt.u32.u64 %0, t; }" : "=r"(a) : "l"(p));
    return a;
}
#define CP_ASYNC16(dst, src) \
    asm volatile("cp.async.cg.shared.global [%0], [%1], 16;" :: "r"(dst), "l"(src))

#define LDSM_X4(r0, r1, r2, r3, a)                                              \
    asm volatile("ldmatrix.sync.aligned.m8n8.x4.shared.b16 {%0,%1,%2,%3}, [%4];" \
                 : "=r"(r0), "=r"(r1), "=r"(r2), "=r"(r3) : "r"(a))

#define MBARRIER_INIT(mb, c) \
    asm volatile("mbarrier.init.shared.b64 [%0], %1;" :: "r"((uint32_t)(mb)), "r"((uint32_t)(c)) : "memory")
#define MBARRIER_ARRIVE(mb) \
    asm volatile("mbarrier.arrive.shared.b64 _, [%0];" :: "r"((uint32_t)(mb)) : "memory")
#define CPASYNC_MBAR_ARRIVE(mb) \
    asm volatile("cp.async.mbarrier.arrive.noinc.shared::cta.b64 [%0];" :: "r"((uint32_t)(mb)) : "memory")

#define MBARRIER_WAIT_PARITY(mb, par) do {                                          \
    uint32_t _mb = (uint32_t)(mb); uint32_t _p = (uint32_t)(par); uint32_t _done;   \
    asm volatile("{\n\t.reg .pred p;\n\t"                                           \
        "mbarrier.try_wait.parity.acquire.cta.shared::cta.b64 p, [%1], %2;\n\t"     \
        "selp.b32 %0, 1, 0, p;\n\t}"                                                \
        : "=r"(_done) : "r"(_mb), "r"(_p) : "memory");                              \
    if (!_done) {                                                                   \
        asm volatile("{\n\t.reg .pred P1;\n\t"                                      \
            "WL_%=:\n\t"                                                            \
            "mbarrier.try_wait.parity.acquire.cta.shared::cta.b64 P1, [%0], %1, 0x989680;\n\t" \
            "@P1 bra.uni WD_%=;\n\t"                                                \
            "bra.uni WL_%=;\n\t"                                                    \
            "WD_%=:\n\t}"                                                           \
            :: "r"(_mb), "r"(_p) : "memory");                                       \
    }                                                                               \
} while (0)

// tile index -> (xg, yg) swizzle (SWZ_G = 8)
__device__ __forceinline__ void tile_to_xy(int tile, int& xg, int& yg) {
    const int tps = 8 * NXT;            // 344
    int stripe = tile / tps;
    int rem    = tile - stripe * tps;
    xg = rem >> 3;
    yg = stripe * 8 + (rem & 7);
}

// ---------------- prequant ----------------
__global__ void wprequant_kernel(const int* __restrict__ w, int n4) {
    int stride = gridDim.x * blockDim.x;
    for (int i = blockIdx.x * blockDim.x + threadIdx.x; i < n4; i += stride) {
        int4 v = reinterpret_cast<const int4*>(w)[i];
        __half2 p0 = __floats2half2_rn((float)v.x, (float)v.y);   // exact
        __half2 p1 = __floats2half2_rn((float)v.z, (float)v.w);
        uint2 pk;
        pk.x = *reinterpret_cast<uint32_t*>(&p0);
        pk.y = *reinterpret_cast<uint32_t*>(&p1);
        reinterpret_cast<uint2*>(g_wh)[i] = pk;
    }
}

__global__ void xprequant_kernel(const float* __restrict__ x, int n4) {
    int stride = gridDim.x * blockDim.x;
    for (int i = blockIdx.x * blockDim.x + threadIdx.x; i < n4; i += stride) {
        float4 v = reinterpret_cast<const float4*>(x)[i];
        __half2 p0 = __floats2half2_rn(v.x, v.y);
        __half2 p1 = __floats2half2_rn(v.z, v.w);
        uint2 pk;
        pk.x = *reinterpret_cast<uint32_t*>(&p0);
        pk.y = *reinterpret_cast<uint32_t*>(&p1);
        reinterpret_cast<uint2*>(g_xh)[i] = pk;
    }
}

// ---------------- GEMM ----------------
#define BM 128
#define BN 256
#define BK 64
#define NTHR 256
#define ATILE 16384                 // 128 rows x 128 B
#define BTILE 32768                 // 256 rows x 128 B
#define STAGEB (ATILE + BTILE)      // 49152
#define NSTAGE 4
#define STAGES_B (NSTAGE * STAGEB)  // 196608
#define SMEMB (STAGES_B + 128)      // + mbarriers

__global__ __launch_bounds__(NTHR, 1)
void w8a16_hmma_kernel(const float* __restrict__ scales,
                       const float* __restrict__ bias,
                       float* __restrict__ out,
                       int M, int N, int K)
{
    extern __shared__ char sm[];
    const uint32_t sb = s2u(sm);
    const uint32_t mb_full  = sb + STAGES_B;        // 4 x 8B
    const uint32_t mb_empty = sb + STAGES_B + 32;   // 4 x 8B
    const int tid  = threadIdx.x;
    const int lane = tid & 31;
    const int warp = tid >> 5;
    const int wm = warp >> 2;            // 0..1 -> m offset 64*wm
    const int wn = warp & 3;             // 0..3 -> n offset 64*wn

    // ---- work assignment ----
    const int lb = blockIdx.x;
    int tile, part, kbeg, nch;
    if (lb < NFULL) {
        tile = lb; part = -1; kbeg = 0; nch = K / BK;            // 64
    } else {
        int idx = lb - NFULL;
        tile = NFULL + idx / SPLITK;
        part = idx % SPLITK;
        kbeg = part * 16;                                        // 64/4 = 16 each
        nch  = 16;
    }
    int xg, yg;
    tile_to_xy(tile, xg, yg);
    const int mbase = yg * BM;
    const int nbase = xg * BN;

    // unified epilogue parameters (bias folded into part-0 partials)
    float*  obase;
    int     ostride;
    float   bmul;
    if (part < 0) {
        obase   = out + (size_t)mbase * N + nbase;
        ostride = N;
        bmul    = 1.0f;
    } else {
        obase   = g_part + ((size_t)part * NTAIL + (tile - NFULL)) * 128 * 256;
        ostride = 256;
        bmul    = (part == 0) ? 1.0f : 0.0f;
    }

    const __half* ag  = g_xh + (size_t)mbase * K;
    const __half* bgp = g_wh + (size_t)nbase * K;

    // ---- mbarrier init ----
    if (tid == 0) {
        #pragma unroll
        for (int s = 0; s < NSTAGE; ++s) {
            MBARRIER_INIT(mb_full  + s * 8, NTHR);
            MBARRIER_INIT(mb_empty + s * 8, 8);
        }
    }
    __syncthreads();

    float acc[4][8][4];
    #pragma unroll
    for (int mi = 0; mi < 4; ++mi)
        #pragma unroll
        for (int ni = 0; ni < 8; ++ni)
            #pragma unroll
            for (int c = 0; c < 4; ++c)
                acc[mi][ni][c] = 0.0f;

    // ldmatrix lane address components (non-trans x4 for both operands)
    const int a_rl = (lane & 7) + ((lane >> 3) & 1) * 8;
    const int a_cb = lane >> 4;
    const int b_rl = (lane & 7) + ((lane >> 4) << 3);
    const int b_cb = (lane >> 3) & 1;

    uint32_t arow[4], am7[4];
    #pragma unroll
    for (int mi = 0; mi < 4; ++mi) {
        int r = wm * 64 + mi * 16 + a_rl;
        arow[mi] = (uint32_t)r * 128;
        am7[mi]  = (uint32_t)(r & 7);
    }
    uint32_t brow[4], bm7[4];
    #pragma unroll
    for (int nj = 0; nj < 4; ++nj) {
        int r = wn * 64 + nj * 16 + b_rl;
        brow[nj] = (uint32_t)r * 128;
        bm7[nj]  = (uint32_t)(r & 7);
    }

    #define ISSUE_STAGE(st, k0) do {                                             \
        uint32_t dstb = sb + (st) * STAGEB;                                      \
        _Pragma("unroll")                                                        \
        for (int cc = 0; cc < 12; ++cc) {                                        \
            int cid  = tid + cc * NTHR;         /* 0..3071 */                    \
            int isB  = cid >= 1024;                                              \
            int rem2 = isB ? (cid - 1024) : cid;                                 \
            int row  = rem2 >> 3;                                                \
            int c    = rem2 & 7;                                                 \
            const __half* src = (isB ? bgp : ag) + (size_t)row * K + (k0) + c * 8; \
            uint32_t dst = dstb + (isB ? ATILE : 0) + row * 128 +                \
                           ((uint32_t)(c ^ (row & 7)) << 4);                     \
            CP_ASYNC16(dst, src);                                                \
        }                                                                        \
        CPASYNC_MBAR_ARRIVE(mb_full + (st) * 8);                                 \
    } while (0)

    // prologue: fill 4 stages with chunks kbeg..kbeg+3
    ISSUE_STAGE(0, kbeg * BK);
    ISSUE_STAGE(1, (kbeg + 1) * BK);
    ISSUE_STAGE(2, (kbeg + 2) * BK);
    ISSUE_STAGE(3, (kbeg + 3) * BK);

    for (int i = 0; i < nch; ++i) {
        const int s = i & 3;
        const int q = (i >> 2) & 1;

        MBARRIER_WAIT_PARITY(mb_full + s * 8, q);

        const uint32_t as = sb + s * STAGEB;
        const uint32_t bs = as + ATILE;

        #pragma unroll
        for (int ks = 0; ks < 4; ++ks) {
            const uint32_t kc2 = (uint32_t)(ks * 2);

            uint32_t bf[4][4];
            #pragma unroll
            for (int nj = 0; nj < 4; ++nj) {
                uint32_t addr = bs + brow[nj] + (((kc2 + b_cb) ^ bm7[nj]) << 4);
                LDSM_X4(bf[nj][0], bf[nj][1], bf[nj][2], bf[nj][3], addr);
            }
            uint32_t af[4][4];
            #pragma unroll
            for (int mi = 0; mi < 4; ++mi) {
                uint32_t addr = as + arow[mi] + (((kc2 + a_cb) ^ am7[mi]) << 4);
                LDSM_X4(af[mi][0], af[mi][1], af[mi][2], af[mi][3], addr);
            }

            #pragma unroll
            for (int mi = 0; mi < 4; ++mi) {
                #pragma unroll
                for (int nj = 0; nj < 4; ++nj) {
                    #pragma unroll
                    for (int h = 0; h < 2; ++h) {
                        const int ni = nj * 2 + h;
                        asm volatile(
                            "mma.sync.aligned.m16n8k16.row.col.f32.f16.f16.f32 "
                            "{%0,%1,%2,%3}, {%4,%5,%6,%7}, {%8,%9}, {%0,%1,%2,%3};\n"
                            : "+f"(acc[mi][ni][0]), "+f"(acc[mi][ni][1]),
                              "+f"(acc[mi][ni][2]), "+f"(acc[mi][ni][3])
                            : "r"(af[mi][0]), "r"(af[mi][1]),
                              "r"(af[mi][2]), "r"(af[mi][3]),
                              "r"(bf[nj][h * 2]), "r"(bf[nj][h * 2 + 1]));
                    }
                }
            }
        }

        if (lane == 0) MBARRIER_ARRIVE(mb_empty + s * 8);

        const int j = i + 4;
        if (j < nch) {
            MBARRIER_WAIT_PARITY(mb_empty + s * 8, q);
            ISSUE_STAGE(s, (kbeg + j) * BK);
        }
    }

    // ---- unified epilogue: y = acc * scales[n] + bias[n]*bmul ----
    #pragma unroll
    for (int mi = 0; mi < 4; ++mi) {
        const int r0 = wm * 64 + mi * 16 + (lane >> 2);
        float* o0 = obase + (size_t)r0 * ostride;
        float* o1 = obase + (size_t)(r0 + 8) * ostride;
        #pragma unroll
        for (int ni = 0; ni < 8; ++ni) {
            const int gn = wn * 64 + ni * 8 + ((lane & 3) << 1);
            const float s0 = scales[nbase + gn], s1 = scales[nbase + gn + 1];
            const float b0 = bias[nbase + gn] * bmul;
            const float b1 = bias[nbase + gn + 1] * bmul;
            float2 v;
            v.x = acc[mi][ni][0] * s0 + b0;
            v.y = acc[mi][ni][1] * s1 + b1;
            *reinterpret_cast<float2*>(o0 + gn) = v;
            v.x = acc[mi][ni][2] * s0 + b0;
            v.y = acc[mi][ni][3] * s1 + b1;
            *reinterpret_cast<float2*>(o1 + gn) = v;
        }
    }
}

// ---------------- tail reduce: out = p0+p1+p2+p3 (bias already in p0) ----
__global__ __launch_bounds__(256)
void tailreduce_kernel(float* __restrict__ out, int N) {
    const int z  = blockIdx.x >> 3;        // 0..43
    const int rg = blockIdx.x & 7;         // row group (16 rows)
    const int tid = threadIdx.x;
    int xg, yg;
    tile_to_xy(NFULL + z, xg, yg);
    const int mbase = yg * BM;
    const int nbase = xg * BN;
    const float* p0 = g_part + ((size_t)0 * NTAIL + z) * 128 * 256;
    const float* p1 = g_part + ((size_t)1 * NTAIL + z) * 128 * 256;
    const float* p2 = g_part + ((size_t)2 * NTAIL + z) * 128 * 256;
    const float* p3 = g_part + ((size_t)3 * NTAIL + z) * 128 * 256;
    #pragma unroll
    for (int r = 0; r < 16; ++r) {
        const int row = rg * 16 + r;
        const int off = row * 256 + tid;
        out[(size_t)(mbase + row) * N + nbase + tid] =
            (p0[off] + p1[off]) + (p2[off] + p3[off]);
    }
}

extern "C" void kernel_launch(void* const* d_in, const int* in_sizes, int n_in,
                              void* d_out, int out_size)
{
    const float* x      = (const float*) d_in[0];
    const int*   w      = (const int*)   d_in[1];   // int8 values in int32 storage
    const float* scales = (const float*) d_in[2];
    const float* bias   = (const float*) d_in[3];
    float*       out    = (float*)       d_out;

    const int N = in_sizes[2];            // 11008
    const int K = in_sizes[1] / N;        // 4096
    const int M = in_sizes[0] / K;        // 4096

    cudaFuncSetAttribute(w8a16_hmma_kernel,
                         cudaFuncAttributeMaxDynamicSharedMemorySize, SMEMB);

    wprequant_kernel<<<2048, 256>>>(w, (N * K) / 4);
    xprequant_kernel<<<2048, 256>>>(x, (M * K) / 4);
    w8a16_hmma_kernel<<<GEMM_GRID, NTHR, SMEMB>>>(scales, bias, out, M, N, K);
    tailreduce_kernel<<<NTAIL * 8, 256>>>(out, N);
}